// round 11
// baseline (speedup 1.0000x reference)
#include <cuda_runtime.h>

// SSIM loss, vertical-first separable blur, ROW-PAIR f32x2 packing:
//   V: thread-per-column scalar 11-tap (proven R4 path), buffers one row and
//      stores row-PAIRS as packed ulls (4 STS.64 / 2 rows, 4 packs / 2 rows).
//   H: window runs along the un-packed axis -> EVERY tap is an aligned ull:
//      11 FMA2 per field per column computes TWO rows at once. Zero pack movs.
//      SSIM evaluated packed (2 rows/op), per-px fast divide.
// Inputs: 2x [16,3,512,512] fp32. Output: 1 fp32 scalar.

typedef unsigned long long ull;
typedef ulonglong2 ull2;

#define NTHR    160
#define TILE_W  128
#define TILE_H  16                   // 8 row-pairs
#define NRP     (TILE_H / 2)         // 8
#define RAD     5
#define KW      11
#define HALO_L  6                    // left pad (even -> aligned ull2 loads)
#define VCOLS   (TILE_W + 2 * RAD)   // 138 columns computed by V
#define STRIDE  140                  // ulls per row-pair row (1120 B)
#define HH      512
#define WW      512
#define PLANES  48
#define GX      (WW / TILE_W)        // 4
#define GY      (HH / TILE_H)        // 32
#define NBLK    (GX * GY * PLANES)   // 6144

__device__ float        g_partials[NBLK];
__device__ unsigned int g_count = 0;

// Gaussian(sigma=1.5) 11 taps, normalized; literals -> immediate-form FFMA.
__device__ __forceinline__ constexpr float GW(int k) {
    return (k == 0 || k == 10) ? 0.00102838f
         : (k == 1 || k == 9)  ? 0.00759877f
         : (k == 2 || k == 8)  ? 0.03600075f
         : (k == 3 || k == 7)  ? 0.10936082f
         : (k == 4 || k == 6)  ? 0.21300554f
         :                       0.26601172f;
}

// ---- f32x2 helpers ----
__device__ __forceinline__ ull F2(float a, float b) {
    ull r; asm("mov.b64 %0,{%1,%2};" : "=l"(r) : "f"(a), "f"(b)); return r;
}
__device__ __forceinline__ void UF2(ull v, float& a, float& b) {
    asm("mov.b64 {%0,%1},%2;" : "=f"(a), "=f"(b) : "l"(v));
}
__device__ __forceinline__ ull FMA2(ull a, ull b, ull c) {
    ull r; asm("fma.rn.f32x2 %0,%1,%2,%3;" : "=l"(r) : "l"(a), "l"(b), "l"(c)); return r;
}
__device__ __forceinline__ ull MUL2(ull a, ull b) {
    ull r; asm("mul.rn.f32x2 %0,%1,%2;" : "=l"(r) : "l"(a), "l"(b)); return r;
}
__device__ __forceinline__ ull ADD2(ull a, ull b) {
    ull r; asm("add.rn.f32x2 %0,%1,%2;" : "=l"(r) : "l"(a), "l"(b)); return r;
}

__global__ void __launch_bounds__(NTHR, 5)
ssim_main(const float* __restrict__ img1, const float* __restrict__ img2,
          float* __restrict__ out)
{
    // Row-pair packed field buffers: element = (value@row2rp, value@row2rp+1).
    __shared__ __align__(16) ull smM1[NRP][STRIDE];
    __shared__ __align__(16) ull smM2[NRP][STRIDE];
    __shared__ __align__(16) ull smQS[NRP][STRIDE];
    __shared__ __align__(16) ull smQX[NRP][STRIDE];

    const int tid   = threadIdx.x;
    const int x0    = blockIdx.x * TILE_W;
    const int y0    = blockIdx.y * TILE_H;
    const int plane = blockIdx.z;
    const size_t pbase = (size_t)plane * (HH * WW);

    // ================= Vertical phase (scalar, R4-proven) =================
    if (tid < VCOLS) {
        const int gx  = x0 + tid - RAD;
        const bool vx = ((unsigned)gx < WW);
        const int gxc = min(max(gx, 0), WW - 1);
        const float* __restrict__ p1 = img1 + pbase + gxc;
        const float* __restrict__ p2 = img2 + pbase + gxc;

        float ra[KW], rb[KW], rs[KW], rp[KW];

        auto loadrow = [&](int i, float& a, float& b) {
            int gy = y0 + i - RAD;
            bool ok = vx && ((unsigned)gy < HH);
            int gyc = min(max(gy, 0), HH - 1);
            size_t off = (size_t)gyc * WW;
            a = ok ? __ldg(p1 + off) : 0.f;
            b = ok ? __ldg(p2 + off) : 0.f;
        };

        #pragma unroll
        for (int i = 0; i < KW - 1; ++i) {
            float a, b; loadrow(i, a, b);
            ra[i] = a; rb[i] = b;
            rs[i] = fmaf(b, b, a * a);
            rp[i] = a * b;
        }
        float ca, cb;
        loadrow(KW - 1, ca, cb);

        float pm1 = 0.f, pm2 = 0.f, pqs = 0.f, pq12 = 0.f;  // even-row stash

        #pragma unroll
        for (int u = 0; u < TILE_H; ++u) {
            const int sl = (u + KW - 1) % KW;
            ra[sl] = ca; rb[sl] = cb;
            rs[sl] = fmaf(cb, cb, ca * ca);
            rp[sl] = ca * cb;
            if (u < TILE_H - 1) loadrow(u + KW, ca, cb);

            float m1 = 0.f, m2 = 0.f, qs = 0.f, q12 = 0.f;
            #pragma unroll
            for (int j = 0; j < KW; ++j) {
                const int s = (u + j) % KW;      // compile-time
                m1  = fmaf(GW(j), ra[s], m1);
                m2  = fmaf(GW(j), rb[s], m2);
                qs  = fmaf(GW(j), rs[s], qs);
                q12 = fmaf(GW(j), rp[s], q12);
            }

            if ((u & 1) == 0) {
                pm1 = m1; pm2 = m2; pqs = qs; pq12 = q12;
            } else {
                const int rp_ = u >> 1;
                const int ci  = tid + 1;   // smem ull index (HALO_L - RAD = 1)
                smM1[rp_][ci] = F2(pm1, m1);
                smM2[rp_][ci] = F2(pm2, m2);
                smQS[rp_][ci] = F2(pqs, qs);
                smQX[rp_][ci] = F2(pq12, q12);
            }
        }
    }
    __syncthreads();

    // ====== Horizontal + SSIM: all taps aligned ulls, 2 rows per FMA2 ======
    float acc = 0.f;
    if (tid < 128) {
        const int cg = tid & 31;    // output cols 4cg..4cg+3
        const int rg = tid >> 5;    // row-pair slot (0..3)
        const int c0 = 4 * cg;

        const ull NEG1 = F2(-1.f, -1.f);
        const ull TWO2 = F2(2.f, 2.f);
        const ull C1v  = F2(1e-4f, 1e-4f);
        const ull C2v  = F2(9e-4f, 9e-4f);

        ull w2[6];
        #pragma unroll
        for (int k = 0; k < 6; ++k) w2[k] = F2(GW(k), GW(k));

        #pragma unroll 1
        for (int rr = 0; rr < 2; ++rr) {
            const int r = rr * 4 + rg;   // row-pair index

            ull bm1[4], bm2[4], bqs[4], bqx[4];

            // Field-major: one window live at a time (16 ulls via 8 LDS.128).
            #pragma unroll
            for (int f = 0; f < 4; ++f) {
                const ull* __restrict__ row =
                    (f == 0) ? &smM1[r][0] : (f == 1) ? &smM2[r][0]
                  : (f == 2) ? &smQS[r][0] : &smQX[r][0];
                ull2 wv[8];
                const ull2* __restrict__ rp2 =
                    reinterpret_cast<const ull2*>(row) + (c0 >> 1);  // ull idx c0
                #pragma unroll
                for (int j = 0; j < 8; ++j) wv[j] = rp2[j];
                const ull* wl = reinterpret_cast<const ull*>(wv);   // idx c0 + i

                ull* dst = (f == 0) ? bm1 : (f == 1) ? bm2 : (f == 2) ? bqs : bqx;
                #pragma unroll
                for (int d = 0; d < 4; ++d) {
                    // taps: smem ull idx c0+d+1 .. c0+d+11 -> local 1+d .. 11+d
                    ull s0 = 0, s1 = 0;
                    #pragma unroll
                    for (int k = 0; k < KW; ++k) {
                        const ull wj = w2[(k < 6) ? k : 10 - k];
                        if (k & 1) s1 = FMA2(wj, wl[d + k + 1], s1);
                        else       s0 = FMA2(wj, wl[d + k + 1], s0);
                    }
                    dst[d] = ADD2(s0, s1);
                }
            }

            // Packed SSIM: each op handles both rows of the pair.
            #pragma unroll
            for (int d = 0; d < 4; ++d) {
                ull mu12 = MUL2(bm1[d], bm2[d]);
                ull mu1s = MUL2(bm1[d], bm1[d]);
                ull mu2s = MUL2(bm2[d], bm2[d]);
                ull s12  = FMA2(mu12, NEG1, bqx[d]);
                ull n1   = FMA2(TWO2, mu12, C1v);
                ull n2   = FMA2(TWO2, s12,  C2v);
                ull S    = ADD2(mu1s, mu2s);
                ull d1   = ADD2(S, C1v);
                ull d2   = ADD2(FMA2(S, NEG1, bqs[d]), C2v);
                ull num  = MUL2(n1, n2);
                ull den  = MUL2(d1, d2);
                float nx, ny, dx, dy;
                UF2(num, nx, ny);
                UF2(den, dx, dy);
                acc += __fdividef(nx, dx);
                acc += __fdividef(ny, dy);
            }
        }
    }

    // ================= Reduction =================
    #pragma unroll
    for (int o = 16; o; o >>= 1)
        acc += __shfl_xor_sync(0xFFFFFFFFu, acc, o);

    __shared__ float ws[NTHR / 32];
    if ((tid & 31) == 0) ws[tid >> 5] = acc;
    __syncthreads();

    const int bid = (blockIdx.z * GY + blockIdx.y) * GX + blockIdx.x;
    __shared__ unsigned int is_last;
    if (tid == 0) {
        float bs = 0.f;
        #pragma unroll
        for (int i = 0; i < NTHR / 32; ++i) bs += ws[i];
        __stcg(&g_partials[bid], bs);
        __threadfence();
        is_last = (atomicAdd(&g_count, 1u) == (unsigned)(NBLK - 1));
    }
    __syncthreads();

    if (is_last) {
        double s = 0.0;
        for (int i = tid; i < NBLK; i += NTHR)
            s += (double)__ldcg(&g_partials[i]);
        #pragma unroll
        for (int o = 16; o; o >>= 1)
            s += __shfl_xor_sync(0xFFFFFFFFu, s, o);
        __shared__ double wd[NTHR / 32];
        if ((tid & 31) == 0) wd[tid >> 5] = s;
        __syncthreads();
        if (tid == 0) {
            double bs = 0.0;
            #pragma unroll
            for (int i = 0; i < NTHR / 32; ++i) bs += wd[i];
            double n = (double)PLANES * HH * WW;
            out[0] = (float)(1.0 - bs / n);
            g_count = 0;   // reset for next graph replay
        }
    }
}

extern "C" void kernel_launch(void* const* d_in, const int* in_sizes, int n_in,
                              void* d_out, int out_size)
{
    (void)in_sizes; (void)n_in; (void)out_size;
    const float* img1 = (const float*)d_in[0];
    const float* img2 = (const float*)d_in[1];
    float* out = (float*)d_out;

    dim3 grid(GX, GY, PLANES);
    ssim_main<<<grid, NTHR>>>(img1, img2, out);
}

// round 12
// speedup vs baseline: 1.0250x; 1.0250x over previous
#include <cuda_runtime.h>

// SSIM loss, vertical-first separable blur (R4 structure + boundary-specialized V):
//   V: thread-per-column vertical 11-tap of {i1,i2,i1^2+i2^2,i1*i2}.
//      - x-halo threads (outside image): write zeros, no loads.
//      - y-interior blocks (30/32): bare LDG at static offsets, ZERO mask/addr ALU.
//      - y-edge blocks: compact rolled shift-ring with bounds checks.
//   H: R4 exact: 4 px/thread, conflict-free float4 smem reads, imm-FFMA taps,
//      scalar SSIM + fast divide; fused deterministic mean.
// Inputs: 2x [16,3,512,512] fp32. Output: 1 fp32 scalar.

#define NTHR    160
#define TILE_W  128
#define TILE_H  16
#define RAD     5
#define KW      11
#define VCOLS   (TILE_W + 2 * RAD)   // 138
#define VSTRIDE 140                  // floats per row, 16B aligned
#define HH      512
#define WW      512
#define PLANES  48
#define GX      (WW / TILE_W)        // 4
#define GY      (HH / TILE_H)        // 32
#define NBLK    (GX * GY * PLANES)   // 6144

__device__ float        g_partials[NBLK];
__device__ unsigned int g_count = 0;

// Gaussian(sigma=1.5) 11 taps, normalized; literals -> immediate-form FFMA.
__device__ __forceinline__ constexpr float GW(int k) {
    return (k == 0 || k == 10) ? 0.00102838f
         : (k == 1 || k == 9)  ? 0.00759877f
         : (k == 2 || k == 8)  ? 0.03600075f
         : (k == 3 || k == 7)  ? 0.10936082f
         : (k == 4 || k == 6)  ? 0.21300554f
         :                       0.26601172f;
}

__global__ void __launch_bounds__(NTHR, 5)
ssim_main(const float* __restrict__ img1, const float* __restrict__ img2,
          float* __restrict__ out)
{
    // SoA field buffers: [field][row][col], rows 16B-aligned.
    __shared__ __align__(16) float smf[4][TILE_H][VSTRIDE];

    const int tid   = threadIdx.x;
    const int x0    = blockIdx.x * TILE_W;
    const int y0    = blockIdx.y * TILE_H;
    const int plane = blockIdx.z;
    const size_t pbase = (size_t)plane * (HH * WW);

    // ================= Vertical phase =================
    if (tid < VCOLS) {
        const int gx  = x0 + tid - RAD;
        const bool vx = ((unsigned)gx < WW);

        if (!vx) {
            // Column entirely outside the image -> vblur of zeros is zero.
            #pragma unroll 1
            for (int u = 0; u < TILE_H; ++u) {
                smf[0][u][tid] = 0.f;
                smf[1][u][tid] = 0.f;
                smf[2][u][tid] = 0.f;
                smf[3][u][tid] = 0.f;
            }
        } else {
            const float* __restrict__ p1 = img1 + pbase + gx;
            const float* __restrict__ p2 = img2 + pbase + gx;
            // Rows loaded: y0-5 .. y0+25. Clean iff all in [0, 512).
            const bool yclean = (y0 >= RAD) && (y0 + TILE_H - 1 + 2 * RAD < HH);

            if (yclean) {
                // ---------- fast path: bare LDG, static offsets ----------
                const float* __restrict__ b1 = p1 + (size_t)(y0 - RAD) * WW;
                const float* __restrict__ b2 = p2 + (size_t)(y0 - RAD) * WW;

                float ra[KW], rb[KW], rs[KW], rp[KW];
                #pragma unroll
                for (int i = 0; i < KW - 1; ++i) {
                    float a = __ldg(b1 + i * WW);
                    float b = __ldg(b2 + i * WW);
                    ra[i] = a; rb[i] = b;
                    rs[i] = fmaf(b, b, a * a);
                    rp[i] = a * b;
                }
                float ca = __ldg(b1 + (KW - 1) * WW);
                float cb = __ldg(b2 + (KW - 1) * WW);

                #pragma unroll
                for (int u = 0; u < TILE_H; ++u) {
                    const int sl = (u + KW - 1) % KW;
                    ra[sl] = ca; rb[sl] = cb;
                    rs[sl] = fmaf(cb, cb, ca * ca);
                    rp[sl] = ca * cb;
                    if (u < TILE_H - 1) {
                        ca = __ldg(b1 + (u + KW) * WW);
                        cb = __ldg(b2 + (u + KW) * WW);
                    }

                    float m1 = 0.f, m2 = 0.f, qs = 0.f, q12 = 0.f;
                    #pragma unroll
                    for (int j = 0; j < KW; ++j) {
                        const int s = (u + j) % KW;      // compile-time
                        m1  = fmaf(GW(j), ra[s], m1);
                        m2  = fmaf(GW(j), rb[s], m2);
                        qs  = fmaf(GW(j), rs[s], qs);
                        q12 = fmaf(GW(j), rp[s], q12);
                    }
                    smf[0][u][tid] = m1;
                    smf[1][u][tid] = m2;
                    smf[2][u][tid] = qs;
                    smf[3][u][tid] = q12;
                }
            } else {
                // ---------- compact y-edge path (2/32 blocks): rolled ----------
                float ra[KW], rb[KW], rs[KW], rp[KW];

                #pragma unroll
                for (int i = 0; i < KW - 1; ++i) {           // static idx (unrolled)
                    int gy = y0 + i - RAD;
                    bool ok = ((unsigned)gy < HH);
                    int gyc = min(max(gy, 0), HH - 1);
                    float a = ok ? __ldg(p1 + (size_t)gyc * WW) : 0.f;
                    float b = ok ? __ldg(p2 + (size_t)gyc * WW) : 0.f;
                    ra[i] = a; rb[i] = b;
                    rs[i] = fmaf(b, b, a * a);
                    rp[i] = a * b;
                }

                #pragma unroll 1
                for (int u = 0; u < TILE_H; ++u) {
                    int gy = y0 + u + KW - 1 - RAD;          // y0+10+u (>= 10)
                    bool ok = (gy < HH);
                    int gyc = min(gy, HH - 1);
                    float ca = ok ? __ldg(p1 + (size_t)gyc * WW) : 0.f;
                    float cb = ok ? __ldg(p2 + (size_t)gyc * WW) : 0.f;
                    ra[KW - 1] = ca; rb[KW - 1] = cb;
                    rs[KW - 1] = fmaf(cb, cb, ca * ca);
                    rp[KW - 1] = ca * cb;

                    float m1 = 0.f, m2 = 0.f, qs = 0.f, q12 = 0.f;
                    #pragma unroll
                    for (int j = 0; j < KW; ++j) {
                        m1  = fmaf(GW(j), ra[j], m1);
                        m2  = fmaf(GW(j), rb[j], m2);
                        qs  = fmaf(GW(j), rs[j], qs);
                        q12 = fmaf(GW(j), rp[j], q12);
                    }
                    smf[0][u][tid] = m1;
                    smf[1][u][tid] = m2;
                    smf[2][u][tid] = qs;
                    smf[3][u][tid] = q12;

                    #pragma unroll
                    for (int j = 0; j < KW - 1; ++j) {       // shift ring
                        ra[j] = ra[j + 1]; rb[j] = rb[j + 1];
                        rs[j] = rs[j + 1]; rp[j] = rp[j + 1];
                    }
                }
            }
        }
    }
    __syncthreads();

    // ================= Horizontal + SSIM phase (R4 exact) =================
    float acc = 0.f;
    if (tid < 128) {
        const int cg = tid & 31;    // output cols 4cg..4cg+3
        const int rg = tid >> 5;    // row slot

        #pragma unroll 1
        for (int rr = 0; rr < 4; ++rr) {
            const int r = rr * 4 + rg;

            float fm1[4], fm2[4], fqs[4], fq12[4];
            #pragma unroll
            for (int d = 0; d < 4; ++d) { fm1[d] = fm2[d] = fqs[d] = fq12[d] = 0.f; }

            // Per field: 4 float4 loads cover cols 4cg..4cg+15 (need ..+13).
            #pragma unroll
            for (int f = 0; f < 4; ++f) {
                const float4* __restrict__ rp4 =
                    reinterpret_cast<const float4*>(&smf[f][r][0]);
                float4 q0 = rp4[cg + 0];
                float4 q1 = rp4[cg + 1];
                float4 q2 = rp4[cg + 2];
                float4 q3 = rp4[cg + 3];
                float cv[16] = { q0.x, q0.y, q0.z, q0.w,
                                 q1.x, q1.y, q1.z, q1.w,
                                 q2.x, q2.y, q2.z, q2.w,
                                 q3.x, q3.y, q3.z, q3.w };
                float* dst = (f == 0) ? fm1 : (f == 1) ? fm2 : (f == 2) ? fqs : fq12;
                #pragma unroll
                for (int d = 0; d < 4; ++d) {
                    float a = 0.f;
                    #pragma unroll
                    for (int k = 0; k < KW; ++k)
                        a = fmaf(GW(k), cv[d + k], a);
                    dst[d] = a;
                }
            }

            #pragma unroll
            for (int d = 0; d < 4; ++d) {
                float mu12 = fm1[d] * fm2[d];
                float mu1s = fm1[d] * fm1[d];
                float mu2s = fm2[d] * fm2[d];
                float s12  = fq12[d] - mu12;
                float n1   = fmaf(2.f, mu12, 1e-4f);
                float n2   = fmaf(2.f, s12,  9e-4f);
                float ttv  = mu1s + mu2s;
                float d1   = ttv + 1e-4f;
                float d2   = (fqs[d] - ttv) + 9e-4f;
                acc += __fdividef(n1 * n2, d1 * d2);
            }
        }
    }

    // ================= Reduction =================
    #pragma unroll
    for (int o = 16; o; o >>= 1)
        acc += __shfl_xor_sync(0xFFFFFFFFu, acc, o);

    __shared__ float ws[NTHR / 32];
    if ((tid & 31) == 0) ws[tid >> 5] = acc;
    __syncthreads();

    const int bid = (blockIdx.z * GY + blockIdx.y) * GX + blockIdx.x;
    __shared__ unsigned int is_last;
    if (tid == 0) {
        float bs = 0.f;
        #pragma unroll
        for (int i = 0; i < NTHR / 32; ++i) bs += ws[i];
        __stcg(&g_partials[bid], bs);
        __threadfence();
        is_last = (atomicAdd(&g_count, 1u) == (unsigned)(NBLK - 1));
    }
    __syncthreads();

    if (is_last) {
        double s = 0.0;
        for (int i = tid; i < NBLK; i += NTHR)
            s += (double)__ldcg(&g_partials[i]);
        #pragma unroll
        for (int o = 16; o; o >>= 1)
            s += __shfl_xor_sync(0xFFFFFFFFu, s, o);
        __shared__ double wd[NTHR / 32];
        if ((tid & 31) == 0) wd[tid >> 5] = s;
        __syncthreads();
        if (tid == 0) {
            double bs = 0.0;
            #pragma unroll
            for (int i = 0; i < NTHR / 32; ++i) bs += wd[i];
            double n = (double)PLANES * HH * WW;
            out[0] = (float)(1.0 - bs / n);
            g_count = 0;   // reset for next graph replay
        }
    }
}

extern "C" void kernel_launch(void* const* d_in, const int* in_sizes, int n_in,
                              void* d_out, int out_size)
{
    (void)in_sizes; (void)n_in; (void)out_size;
    const float* img1 = (const float*)d_in[0];
    const float* img2 = (const float*)d_in[1];
    float* out = (float*)d_out;

    dim3 grid(GX, GY, PLANES);
    ssim_main<<<grid, NTHR>>>(img1, img2, out);
}